// round 13
// baseline (speedup 1.0000x reference)
#include <cuda_runtime.h>

// ---------------- problem constants ----------------
#define BANDS 64
#define CHA   64
#define NPIX  16384
#define RR    3
#define NITE  20
#define NT    128                 // pixel sub-tile width (threads per block)
#define SUBT  4                   // sub-tiles per block
#define GROUPN (NT*SUBT)          // 512 pixels per block
#define NGROUPS (NPIX/GROUPN)     // 32 groups per band
#define NCHUNK 4                  // band chunks / streams (3 side streams passed the mem checkpoint in R9)
#define BPC   (BANDS/NCHUNK)      // 16 bands per chunk
#define TOTELEM ((size_t)BANDS*CHA*NPIX)  // 67,108,864
typedef unsigned long long ULL;

// ---------------- device scratch (no allocs allowed) ----------------
__device__ float g_utl[BANDS*RR*NPIX];             // 12.6 MB
__device__ float g_Gpart[BANDS*NGROUPS*CHA*CHA];   // 33.5 MB
__device__ float g_V[BANDS*CHA*CHA];               // 1 MB   (warm-start eigenbasis)
__device__ float g_Ur[2][BANDS*CHA*RR];            // double-buffered top-3 basis
__device__ float g_lossPart[NITE*BANDS*NGROUPS*2]; // per-iteration loss partials
__device__ float g_wpart[1024];
__device__ float g_rho0;

// ---------------- packed f32x2 helpers (SASS FFMA2; PTX-only pattern) ----------------
__device__ __forceinline__ void ffma2(ULL& acc, ULL a, ULL b) {
    asm("fma.rn.f32x2 %0, %1, %2, %0;" : "+l"(acc) : "l"(a), "l"(b));
}
__device__ __forceinline__ void unpack2(ULL v, float& lo, float& hi) {
    unsigned int a, b;
    asm("mov.b64 {%0, %1}, %2;" : "=r"(a), "=r"(b) : "l"(v));
    lo = __uint_as_float(a); hi = __uint_as_float(b);
}

// ---------------- mean(W) reduction ----------------
__global__ void wsum_part_kernel(const float* __restrict__ W) {
    __shared__ float sred[256];
    float s = 0.f;
    size_t stride = (size_t)gridDim.x * blockDim.x;
    for (size_t i = (size_t)blockIdx.x*blockDim.x + threadIdx.x; i < TOTELEM; i += stride)
        s += W[i];
    sred[threadIdx.x] = s; __syncthreads();
    for (int o = 128; o > 0; o >>= 1) {
        if (threadIdx.x < o) sred[threadIdx.x] += sred[threadIdx.x+o];
        __syncthreads();
    }
    if (threadIdx.x == 0) g_wpart[blockIdx.x] = sred[0];
}

__global__ void wsum_final_kernel() {
    __shared__ float sred[256];
    float s = 0.f;
    for (int i = threadIdx.x; i < 1024; i += 256) s += g_wpart[i];
    sred[threadIdx.x] = s; __syncthreads();
    for (int o = 128; o > 0; o >>= 1) {
        if (threadIdx.x < o) sred[threadIdx.x] += sred[threadIdx.x+o];
        __syncthreads();
    }
    if (threadIdx.x == 0) g_rho0 = 0.5f * sred[0] / (float)TOTELEM;
}

// ---------------- gram accumulate, paired-n FFMA2, conflict-free ----------------
__device__ __forceinline__ void gram_acc2(const float (*sL)[NT+2], ULL acc[8][4], int ty, int tx) {
    #pragma unroll 2
    for (int n = 0; n < NT; n += 2) {
        ULL a2[8], b2[4];
        #pragma unroll
        for (int i = 0; i < 8; i++) a2[i] = *(const ULL*)&sL[ty + 8*i][n];
        #pragma unroll
        for (int j = 0; j < 4; j++) b2[j] = *(const ULL*)&sL[tx + 16*j][n];
        #pragma unroll
        for (int i = 0; i < 8; i++)
            #pragma unroll
            for (int j = 0; j < 4; j++)
                ffma2(acc[i][j], a2[i], b2[j]);
    }
}

__device__ __forceinline__ void gram_store2(float* out, ULL acc[8][4], int ty, int tx) {
    #pragma unroll
    for (int i = 0; i < 8; i++)
        #pragma unroll
        for (int j = 0; j < 4; j++) {
            float lo, hi; unpack2(acc[i][j], lo, hi);
            out[(ty + 8*i)*CHA + tx + 16*j] = lo + hi;
        }
}

// ---------------- G0 = x x^T (partials) ----------------
__global__ __launch_bounds__(NT) void syrk0_kernel(const float* __restrict__ src, int bandOff) {
    int b = bandOff + blockIdx.y, grp = blockIdx.x, tid = threadIdx.x;
    __shared__ float sL[CHA][NT+2];
    int ty = tid >> 4, tx = tid & 15;
    ULL acc[8][4];
    #pragma unroll
    for (int i = 0; i < 8; i++)
        #pragma unroll
        for (int j = 0; j < 4; j++) acc[i][j] = 0ULL;

    size_t base = (size_t)b*CHA*NPIX + (size_t)grp*GROUPN;
    for (int st = 0; st < SUBT; st++) {
        __syncthreads();
        #pragma unroll 4
        for (int c = 0; c < CHA; c++)
            sL[c][tid] = src[base + (size_t)c*NPIX + st*NT + tid];
        __syncthreads();
        gram_acc2(sL, acc, ty, tx);
    }
    gram_store2(g_Gpart + ((size_t)(b*NGROUPS + grp))*CHA*CHA, acc, ty, tx);
}

// ---------------- warm-started, thresholded Jacobi eigensolver ----------------
// Norms/threshold computed ONCE per launch (||A||F invariant under rotations);
// sweeps terminate via the all-inactive break, which is barrier-protected
// against the next sweep's sSweepActive reset (the R10 crash).
#define ETH 512
__global__ __launch_bounds__(ETH) void eig_kernel(int t, int bandOff) {
    int b = bandOff + blockIdx.x, tid = threadIdx.x;
    extern __shared__ float esm[];
    float (*A)[CHA+1] = (float(*)[CHA+1])esm;                   // 64x65
    float (*V)[CHA+1] = (float(*)[CHA+1])(esm + CHA*(CHA+1));   // 64x65
    float (*V0)[CHA]  = (float(*)[CHA]) (esm + 2*CHA*(CHA+1));  // 64x64
    __shared__ float cs[32], sn[32];
    __shared__ int   pA[32], qA[32];
    __shared__ float red1[ETH/32], red2[ETH/32];
    __shared__ float threshsh;
    __shared__ unsigned int sMask;
    __shared__ int   sSweepActive;
    __shared__ float sdiag[CHA];
    __shared__ int   tidx3[3];

    // 1) reduce gram partials for this band
    const float* P = g_Gpart + (size_t)b*NGROUPS*CHA*CHA;
    for (int e = tid; e < CHA*CHA; e += ETH) {
        float s = 0.f;
        #pragma unroll
        for (int g2 = 0; g2 < NGROUPS; g2++) s += P[(size_t)g2*CHA*CHA + e];
        A[e>>6][e&63] = s;
        if (t > 0) V0[e>>6][e&63] = g_V[(size_t)b*CHA*CHA + e];
    }
    __syncthreads();

    int mi = tid >> 3;          // 0..63
    int mj = (tid & 7) * 8;     // 0,8,..,56

    // 2) warm start: A <- V0^T A V0
    if (t > 0) {
        float tac[8];
        #pragma unroll
        for (int j = 0; j < 8; j++) tac[j] = 0.f;
        for (int k = 0; k < CHA; k++) {
            float a = A[mi][k];
            #pragma unroll
            for (int j = 0; j < 8; j++) tac[j] = fmaf(a, V0[k][mj+j], tac[j]);
        }
        #pragma unroll
        for (int j = 0; j < 8; j++) V[mi][mj+j] = tac[j];     // V holds T = A*V0
        __syncthreads();
        float tac2[8];
        #pragma unroll
        for (int j = 0; j < 8; j++) tac2[j] = 0.f;
        for (int k = 0; k < CHA; k++) {
            float a = V0[k][mi];
            #pragma unroll
            for (int j = 0; j < 8; j++) tac2[j] = fmaf(a, V[k][mj+j], tac2[j]);
        }
        __syncthreads();
        #pragma unroll
        for (int j = 0; j < 8; j++) A[mi][mj+j] = tac2[j];    // A <- V0^T T
        __syncthreads();
    }

    // 3) V <- I ; one-time norms + threshold
    {
        float off = 0.f, dg = 0.f;
        for (int e = tid; e < CHA*CHA; e += ETH) {
            int i = e >> 6, j = e & 63;
            V[i][j] = (i == j) ? 1.f : 0.f;
            float v = A[i][j];
            if (i == j) dg += v*v; else off += v*v;
        }
        #pragma unroll
        for (int o = 16; o > 0; o >>= 1) {
            off += __shfl_xor_sync(0xffffffffu, off, o);
            dg  += __shfl_xor_sync(0xffffffffu, dg, o);
        }
        if ((tid & 31) == 0) { red1[tid>>5] = off; red2[tid>>5] = dg; }
        __syncthreads();
        if (tid == 0) {
            float o2 = 0.f, d2 = 0.f;
            for (int i2 = 0; i2 < ETH/32; i2++) { o2 += red1[i2]; d2 += red2[i2]; }
            float tot = o2 + d2;
            threshsh = 5e-14f * tot;      // apq <= ~2.2e-7*||A||F
            if (o2 <= 1e-10f * tot) threshsh = 3.4e38f;   // already converged -> all-inactive
        }
        __syncthreads();
    }
    float thr = threshsh;

    int maxsweep = (t == 0) ? 13 : 5;
    for (int sweep = 0; sweep < maxsweep; sweep++) {
        if (tid == 0) sSweepActive = 0;
        __syncthreads();

        for (int r = 0; r < 63; r++) {
            if (tid < 32) {
                int p = (tid == 0) ? 0 : ((tid - 1 + r) % 63) + 1;
                int qpos = 63 - tid;
                int q = ((qpos - 1 + r) % 63) + 1;
                float app = A[p][p], aqq = A[q][q], apq = A[p][q];
                float c = 1.f, s = 0.f;
                bool active = (apq*apq > thr);
                if (active) {
                    float tau = (aqq - app) / (2.f * apq);
                    float tt = 1.f / (fabsf(tau) + sqrtf(fmaf(tau, tau, 1.f)));
                    if (tau < 0.f) tt = -tt;
                    c = rsqrtf(fmaf(tt, tt, 1.f));
                    s = tt * c;
                }
                cs[tid] = c; sn[tid] = s; pA[tid] = p; qA[tid] = q;
                unsigned int m = __ballot_sync(0xffffffffu, active);
                if (tid == 0) { sMask = m; if (m) sSweepActive = 1; }
            }
            __syncthreads();
            if (sMask != 0u) {
                // row updates (J^T A)
                for (int task = tid; task < 2048; task += ETH) {
                    int pr = task >> 6, j = task & 63;
                    float s = sn[pr];
                    if (s != 0.f) {
                        float c = cs[pr];
                        int p = pA[pr], q = qA[pr];
                        float a0 = A[p][j], a1 = A[q][j];
                        A[p][j] = c*a0 - s*a1;
                        A[q][j] = s*a0 + c*a1;
                    }
                }
                __syncthreads();
                // column updates (A J) + eigenvector accumulation (V J)
                for (int task = tid; task < 4096; task += ETH) {
                    int sel = task >> 11, sub = task & 2047;
                    int pr = sub >> 6, i = sub & 63;
                    float s = sn[pr];
                    if (s != 0.f) {
                        float c = cs[pr];
                        int p = pA[pr], q = qA[pr];
                        if (sel == 0) {
                            float a0 = A[i][p], a1 = A[i][q];
                            A[i][p] = c*a0 - s*a1;
                            A[i][q] = s*a0 + c*a1;
                        } else {
                            float a0 = V[i][p], a1 = V[i][q];
                            V[i][p] = c*a0 - s*a1;
                            V[i][q] = s*a0 + c*a1;
                        }
                    }
                }
            }
            __syncthreads();
        }
        // RACE FIX (R10 crash): read the flag, THEN barrier, THEN break.
        int sweepDone = (sSweepActive == 0);
        __syncthreads();
        if (sweepDone) break;   // full sweep, zero rotations -> converged
    }

    // 4) eigenvalue estimates (diag)
    if (tid < CHA) sdiag[tid] = A[tid][tid];
    __syncthreads();

    if (t > 0) {
        float fac[8];
        #pragma unroll
        for (int j = 0; j < 8; j++) fac[j] = 0.f;
        for (int k = 0; k < CHA; k++) {
            float a = V0[mi][k];
            #pragma unroll
            for (int j = 0; j < 8; j++) fac[j] = fmaf(a, V[k][mj+j], fac[j]);
        }
        __syncthreads();
        #pragma unroll
        for (int j = 0; j < 8; j++) A[mi][mj+j] = fac[j];
        __syncthreads();
    }
    float (*VF)[CHA+1] = (t > 0) ? A : V;

    // 5) store basis + top-3 columns (double-buffered Ur)
    for (int e = tid; e < CHA*CHA; e += ETH)
        g_V[(size_t)b*CHA*CHA + e] = VF[e>>6][e&63];

    if (tid == 0) {
        float v0 = -1e30f, v1 = -1e30f, v2 = -1e30f;
        int i0 = 0, i1 = 0, i2 = 0;
        for (int k = 0; k < CHA; k++) {
            float d = sdiag[k];
            if (d > v0)      { v2=v1; i2=i1; v1=v0; i1=i0; v0=d; i0=k; }
            else if (d > v1) { v2=v1; i2=i1; v1=d;  i1=k; }
            else if (d > v2) { v2=d;  i2=k; }
        }
        tidx3[0] = i0; tidx3[1] = i1; tidx3[2] = i2;
    }
    __syncthreads();
    float* urOut = g_Ur[t & 1];
    for (int e = tid; e < CHA*RR; e += ETH) {
        int c = e / RR, rr2 = e % RR;
        urOut[(size_t)b*CHA*RR + e] = VF[c][tidx3[rr2]];
    }
}

// ---------------- fused: reconstruct L_t, utl_t, losses, L_{t+1} gram ----------------
__global__ __launch_bounds__(NT) void fused_kernel(
    const float* __restrict__ x, const float* __restrict__ W,
    float apPrev, float apCur, int t, int last, float* __restrict__ outUV, int bandOff)
{
    int b = bandOff + blockIdx.y, grp = blockIdx.x, tid = threadIdx.x;
    extern __shared__ float fsm[];
    float (*xs)[NT+2] = (float(*)[NT+2])fsm;                 // x tile, becomes L_{t+1} tile
    float (*ws)[NT+2] = (float(*)[NT+2])(fsm + CHA*(NT+2));  // W tile
    __shared__ float sUrC[CHA*RR], sUrP[CHA*RR];
    __shared__ float sred[8];

    const float* urC = g_Ur[t & 1];
    const float* urP = g_Ur[(t - 1) & 1];
    for (int e = tid; e < CHA*RR; e += NT) {
        sUrC[e] = urC[(size_t)b*CHA*RR + e];
        if (t > 0) sUrP[e] = urP[(size_t)b*CHA*RR + e];
    }
    float rhoP = g_rho0 * apPrev;
    float rhoC = g_rho0 * apCur;
    int ty = tid >> 4, tx = tid & 15;
    ULL acc[8][4];
    #pragma unroll
    for (int i = 0; i < 8; i++)
        #pragma unroll
        for (int j = 0; j < 4; j++) acc[i][j] = 0ULL;
    float lossF = 0.f, lossU = 0.f;
    __syncthreads();

    #pragma unroll 1
    for (int st = 0; st < SUBT; st++) {
        int pix = grp*GROUPN + st*NT + tid;
        size_t base = (size_t)b*CHA*NPIX + pix;
        __syncthreads();
        #pragma unroll 8
        for (int c = 0; c < CHA; c++) {
            size_t idx = base + (size_t)c*NPIX;
            xs[c][tid] = x[idx];
            ws[c][tid] = W[idx];
        }
        float u0 = 0.f, u1 = 0.f, u2 = 0.f;
        if (t == 0) {
            #pragma unroll 8
            for (int c = 0; c < CHA; c++) {
                float v = xs[c][tid];
                u0 = fmaf(sUrC[c*3+0], v, u0);
                u1 = fmaf(sUrC[c*3+1], v, u1);
                u2 = fmaf(sUrC[c*3+2], v, u2);
            }
        } else {
            size_t ub = (size_t)b*RR*NPIX + pix;
            float p0 = g_utl[ub];
            float p1 = g_utl[ub + NPIX];
            float p2 = g_utl[ub + 2*NPIX];
            #pragma unroll 4
            for (int c = 0; c < CHA; c++) {
                float xv = xs[c][tid], wv = ws[c][tid];
                float uvp = fmaf(sUrP[c*3+0], p0, fmaf(sUrP[c*3+1], p1, sUrP[c*3+2]*p2));
                float d = uvp - xv;
                float mu = __fdividef(rhoP, wv + rhoP);
                float lv = fmaf(mu, d, xv);
                u0 = fmaf(sUrC[c*3+0], lv, u0);
                u1 = fmaf(sUrC[c*3+1], lv, u1);
                u2 = fmaf(sUrC[c*3+2], lv, u2);
            }
        }
        lossU += u0*u0 + u1*u1 + u2*u2;

        if (!last) {
            size_t ub = (size_t)b*RR*NPIX + pix;
            g_utl[ub]          = u0;
            g_utl[ub + NPIX]   = u1;
            g_utl[ub + 2*NPIX] = u2;
            #pragma unroll 4
            for (int c = 0; c < CHA; c++) {
                float xv = xs[c][tid], wv = ws[c][tid];
                float uv = fmaf(sUrC[c*3+0], u0, fmaf(sUrC[c*3+1], u1, sUrC[c*3+2]*u2));
                float d = uv - xv;
                lossF = fmaf(wv*d, d, lossF);
                float mu = __fdividef(rhoC, wv + rhoC);
                xs[c][tid] = fmaf(mu, d, xv);
            }
            __syncthreads();
            gram_acc2((const float(*)[NT+2])xs, acc, ty, tx);
        } else {
            #pragma unroll 4
            for (int c = 0; c < CHA; c++) {
                float xv = xs[c][tid], wv = ws[c][tid];
                float uv = fmaf(sUrC[c*3+0], u0, fmaf(sUrC[c*3+1], u1, sUrC[c*3+2]*u2));
                float d = uv - xv;
                lossF = fmaf(wv*d, d, lossF);
                outUV[base + (size_t)c*NPIX] = uv;
            }
        }
    }

    #pragma unroll
    for (int o = 16; o > 0; o >>= 1) {
        lossF += __shfl_xor_sync(0xffffffffu, lossF, o);
        lossU += __shfl_xor_sync(0xffffffffu, lossU, o);
    }
    if ((tid & 31) == 0) { sred[tid>>5] = lossF; sred[4 + (tid>>5)] = lossU; }
    __syncthreads();
    if (tid == 0) {
        float f = sred[0]+sred[1]+sred[2]+sred[3];
        float u = sred[4]+sred[5]+sred[6]+sred[7];
        size_t gi = (size_t)t*BANDS*NGROUPS + (size_t)b*NGROUPS + grp;
        g_lossPart[2*gi]   = f;
        g_lossPart[2*gi+1] = u;
    }

    if (!last)
        gram_store2(g_Gpart + ((size_t)(b*NGROUPS + grp))*CHA*CHA, acc, ty, tx);
}

// ---------------- all per-iteration loss scalars -> d_out tail (after join) ----------------
__global__ void final_loss_kernel(float* __restrict__ out) {
    __shared__ float sf[256], su[256];
    int t = blockIdx.x;
    float f = 0.f, u = 0.f;
    const float* p = g_lossPart + (size_t)t*BANDS*NGROUPS*2;
    for (int i = threadIdx.x; i < BANDS*NGROUPS; i += 256) {
        f += p[2*i];
        u += p[2*i+1];
    }
    sf[threadIdx.x] = f; su[threadIdx.x] = u; __syncthreads();
    for (int o = 128; o > 0; o >>= 1) {
        if (threadIdx.x < o) { sf[threadIdx.x] += sf[threadIdx.x+o]; su[threadIdx.x] += su[threadIdx.x+o]; }
        __syncthreads();
    }
    if (threadIdx.x == 0) {
        float inv = 1.f / (float)TOTELEM;
        out[TOTELEM + t]        = sf[0] * inv;   // loss_F
        out[TOTELEM + NITE + t] = su[0] * inv;   // loss
    }
}

// ---------------- launch: 4 band-chunks on 4 streams, fork/join via events ----------------
extern "C" void kernel_launch(void* const* d_in, const int* in_sizes, int n_in,
                              void* d_out, int out_size) {
    (void)in_sizes; (void)n_in; (void)out_size;
    const float* x = (const float*)d_in[0];
    const float* W = (const float*)d_in[1];
    float* out = (float*)d_out;

    const int ESMEM = (2*CHA*(CHA+1) + CHA*CHA) * (int)sizeof(float);  // 49664 B
    const int FSMEM = 2*CHA*(NT+2) * (int)sizeof(float);               // 66560 B

    static cudaStream_t side[NCHUNK-1];
    static cudaEvent_t  evFork, evJoin[NCHUNK-1];
    static int init_done = 0;
    if (!init_done) {
        cudaFuncSetAttribute(eig_kernel,   cudaFuncAttributeMaxDynamicSharedMemorySize, ESMEM);
        cudaFuncSetAttribute(fused_kernel, cudaFuncAttributeMaxDynamicSharedMemorySize, FSMEM);
        for (int i = 0; i < NCHUNK-1; i++)
            cudaStreamCreateWithFlags(&side[i], cudaStreamNonBlocking);
        cudaEventCreateWithFlags(&evFork, cudaEventDisableTiming);
        for (int i = 0; i < NCHUNK-1; i++)
            cudaEventCreateWithFlags(&evJoin[i], cudaEventDisableTiming);
        init_done = 1;
    }

    // prologue on the main (capture) stream
    wsum_part_kernel<<<1024, 256>>>(W);
    wsum_final_kernel<<<1, 256>>>();

    // fork
    cudaEventRecord(evFork, 0);
    for (int i = 0; i < NCHUNK-1; i++)
        cudaStreamWaitEvent(side[i], evFork, 0);

    // independent per-chunk chains
    for (int ck = 0; ck < NCHUNK; ck++) {
        cudaStream_t st = (ck == 0) ? (cudaStream_t)0 : side[ck-1];
        int off = ck * BPC;
        dim3 gGram(NGROUPS, BPC);
        syrk0_kernel<<<gGram, NT, 0, st>>>(x, off);
        float ap = 1.0f, apPrev = 1.0f;
        for (int t = 0; t < NITE; t++) {
            eig_kernel<<<BPC, ETH, ESMEM, st>>>(t, off);
            fused_kernel<<<gGram, NT, FSMEM, st>>>(x, W, apPrev, ap, t,
                                                   (t == NITE-1) ? 1 : 0, out, off);
            apPrev = ap;
            ap *= 1.05f;   // matches reference's fp32 rho *= 1.05 recurrence
        }
    }

    // join
    for (int i = 0; i < NCHUNK-1; i++) {
        cudaEventRecord(evJoin[i], side[i]);
        cudaStreamWaitEvent((cudaStream_t)0, evJoin[i], 0);
    }

    // all 40 loss scalars in one launch
    final_loss_kernel<<<NITE, 256>>>(out);
}

// round 15
// speedup vs baseline: 1.0818x; 1.0818x over previous
#include <cuda_runtime.h>

// ---------------- problem constants ----------------
#define BANDS 64
#define CHA   64
#define NPIX  16384
#define RR    3
#define NITE  20
#define NT    128                 // pixel sub-tile width (threads per block)
#define SUBT  4                   // sub-tiles per block
#define GROUPN (NT*SUBT)          // 512 pixels per block
#define NGROUPS (NPIX/GROUPN)     // 32 groups per band
#define NCHUNK 4                  // band chunks / streams (3 side streams passed the mem checkpoint)
#define BPC   (BANDS/NCHUNK)      // 16 bands per chunk
#define TOTELEM ((size_t)BANDS*CHA*NPIX)  // 67,108,864
#define LDA   (CHA+1)             // 65: smem row stride for eig matrices
typedef unsigned long long ULL;

// ---------------- device scratch (no allocs allowed) ----------------
__device__ float g_utl[BANDS*RR*NPIX];             // 12.6 MB
__device__ float g_Gpart[BANDS*NGROUPS*CHA*CHA];   // 33.5 MB
__device__ float g_V[BANDS*CHA*CHA];               // 1 MB   (warm-start eigenbasis)
__device__ float g_Ur[2][BANDS*CHA*RR];            // double-buffered top-3 basis
__device__ float g_lossPart[NITE*BANDS*NGROUPS*2]; // per-iteration loss partials
__device__ float g_wpart[1024];
__device__ float g_rho0;

// ---------------- packed f32x2 helpers (SASS FFMA2; PTX-only pattern) ----------------
__device__ __forceinline__ void ffma2(ULL& acc, ULL a, ULL b) {
    asm("fma.rn.f32x2 %0, %1, %2, %0;" : "+l"(acc) : "l"(a), "l"(b));
}
__device__ __forceinline__ void unpack2(ULL v, float& lo, float& hi) {
    unsigned int a, b;
    asm("mov.b64 {%0, %1}, %2;" : "=r"(a), "=r"(b) : "l"(v));
    lo = __uint_as_float(a); hi = __uint_as_float(b);
}

// ---------------- mean(W) reduction ----------------
__global__ void wsum_part_kernel(const float* __restrict__ W) {
    __shared__ float sred[256];
    float s = 0.f;
    size_t stride = (size_t)gridDim.x * blockDim.x;
    for (size_t i = (size_t)blockIdx.x*blockDim.x + threadIdx.x; i < TOTELEM; i += stride)
        s += W[i];
    sred[threadIdx.x] = s; __syncthreads();
    for (int o = 128; o > 0; o >>= 1) {
        if (threadIdx.x < o) sred[threadIdx.x] += sred[threadIdx.x+o];
        __syncthreads();
    }
    if (threadIdx.x == 0) g_wpart[blockIdx.x] = sred[0];
}

__global__ void wsum_final_kernel() {
    __shared__ float sred[256];
    float s = 0.f;
    for (int i = threadIdx.x; i < 1024; i += 256) s += g_wpart[i];
    sred[threadIdx.x] = s; __syncthreads();
    for (int o = 128; o > 0; o >>= 1) {
        if (threadIdx.x < o) sred[threadIdx.x] += sred[threadIdx.x+o];
        __syncthreads();
    }
    if (threadIdx.x == 0) g_rho0 = 0.5f * sred[0] / (float)TOTELEM;
}

// ---------------- gram accumulate, paired-n FFMA2, conflict-free ----------------
__device__ __forceinline__ void gram_acc2(const float (*sL)[NT+2], ULL acc[8][4], int ty, int tx) {
    #pragma unroll 2
    for (int n = 0; n < NT; n += 2) {
        ULL a2[8], b2[4];
        #pragma unroll
        for (int i = 0; i < 8; i++) a2[i] = *(const ULL*)&sL[ty + 8*i][n];
        #pragma unroll
        for (int j = 0; j < 4; j++) b2[j] = *(const ULL*)&sL[tx + 16*j][n];
        #pragma unroll
        for (int i = 0; i < 8; i++)
            #pragma unroll
            for (int j = 0; j < 4; j++)
                ffma2(acc[i][j], a2[i], b2[j]);
    }
}

__device__ __forceinline__ void gram_store2(float* out, ULL acc[8][4], int ty, int tx) {
    #pragma unroll
    for (int i = 0; i < 8; i++)
        #pragma unroll
        for (int j = 0; j < 4; j++) {
            float lo, hi; unpack2(acc[i][j], lo, hi);
            out[(ty + 8*i)*CHA + tx + 16*j] = lo + hi;
        }
}

// ---------------- G0 = x x^T (partials) ----------------
__global__ __launch_bounds__(NT) void syrk0_kernel(const float* __restrict__ src, int bandOff) {
    int b = bandOff + blockIdx.y, grp = blockIdx.x, tid = threadIdx.x;
    __shared__ float sL[CHA][NT+2];
    int ty = tid >> 4, tx = tid & 15;
    ULL acc[8][4];
    #pragma unroll
    for (int i = 0; i < 8; i++)
        #pragma unroll
        for (int j = 0; j < 4; j++) acc[i][j] = 0ULL;

    size_t base = (size_t)b*CHA*NPIX + (size_t)grp*GROUPN;
    for (int st = 0; st < SUBT; st++) {
        __syncthreads();
        #pragma unroll 4
        for (int c = 0; c < CHA; c++)
            sL[c][tid] = src[base + (size_t)c*NPIX + st*NT + tid];
        __syncthreads();
        gram_acc2(sL, acc, ty, tx);
    }
    gram_store2(g_Gpart + ((size_t)(b*NGROUPS + grp))*CHA*CHA, acc, ty, tx);
}

// ---------------- warm-started Jacobi, fused 2x2-block rounds (2 barriers/round) ----------------
// Round r's 32 pairs partition the 64 indices, so A' = J^T A J splits into
// 32x32 independent 2x2 blocks -> one ping-pong update phase. V's column
// rotation is ownership-disjoint (in-place safe) and rides the same phase.
#define ETH 512
__global__ __launch_bounds__(ETH) void eig_kernel(int t, int bandOff) {
    int b = bandOff + blockIdx.x, tid = threadIdx.x;
    extern __shared__ float esm[];
    float* Abuf0 = esm;                       // 64x65
    float* Abuf1 = esm + CHA*LDA;             // 64x65
    float* Vv    = esm + 2*CHA*LDA;           // 64x65
    float* V0v   = esm + 3*CHA*LDA;           // 64x64
    __shared__ float cs[32], sn[32];
    __shared__ int   pA[32], qA[32];
    __shared__ float red1[ETH/32], red2[ETH/32];
    __shared__ float threshsh;
    __shared__ unsigned int sMask;
    __shared__ int   sSweepActive;
    __shared__ float sdiag[CHA];
    __shared__ int   tidx3[3];

    // 1) reduce gram partials for this band into Abuf0
    const float* P = g_Gpart + (size_t)b*NGROUPS*CHA*CHA;
    for (int e = tid; e < CHA*CHA; e += ETH) {
        float s = 0.f;
        #pragma unroll
        for (int g2 = 0; g2 < NGROUPS; g2++) s += P[(size_t)g2*CHA*CHA + e];
        Abuf0[(e>>6)*LDA + (e&63)] = s;
        if (t > 0) V0v[e] = g_V[(size_t)b*CHA*CHA + e];
    }
    __syncthreads();

    int mi = tid >> 3;          // 0..63
    int mj = (tid & 7) * 8;     // 0,8,..,56

    // 2) warm start: A <- V0^T A V0  (temp = Abuf1)
    if (t > 0) {
        float tac[8];
        #pragma unroll
        for (int j = 0; j < 8; j++) tac[j] = 0.f;
        for (int k = 0; k < CHA; k++) {
            float a = Abuf0[mi*LDA + k];
            #pragma unroll
            for (int j = 0; j < 8; j++) tac[j] = fmaf(a, V0v[k*CHA + mj+j], tac[j]);
        }
        #pragma unroll
        for (int j = 0; j < 8; j++) Abuf1[mi*LDA + mj+j] = tac[j];   // T = A*V0
        __syncthreads();
        float tac2[8];
        #pragma unroll
        for (int j = 0; j < 8; j++) tac2[j] = 0.f;
        for (int k = 0; k < CHA; k++) {
            float a = V0v[k*CHA + mi];
            #pragma unroll
            for (int j = 0; j < 8; j++) tac2[j] = fmaf(a, Abuf1[k*LDA + mj+j], tac2[j]);
        }
        __syncthreads();
        #pragma unroll
        for (int j = 0; j < 8; j++) Abuf0[mi*LDA + mj+j] = tac2[j];  // A <- V0^T T
        __syncthreads();
    }

    // 3) V <- I ; one-time norms + threshold (||A||F invariant under rotations)
    {
        float off = 0.f, dg = 0.f;
        for (int e = tid; e < CHA*CHA; e += ETH) {
            int i = e >> 6, j = e & 63;
            Vv[i*LDA + j] = (i == j) ? 1.f : 0.f;
            float v = Abuf0[i*LDA + j];
            if (i == j) dg += v*v; else off += v*v;
        }
        #pragma unroll
        for (int o = 16; o > 0; o >>= 1) {
            off += __shfl_xor_sync(0xffffffffu, off, o);
            dg  += __shfl_xor_sync(0xffffffffu, dg, o);
        }
        if ((tid & 31) == 0) { red1[tid>>5] = off; red2[tid>>5] = dg; }
        __syncthreads();
        if (tid == 0) {
            float o2 = 0.f, d2 = 0.f;
            for (int i2 = 0; i2 < ETH/32; i2++) { o2 += red1[i2]; d2 += red2[i2]; }
            float tot = o2 + d2;
            threshsh = 5e-14f * tot;      // apq <= ~2.2e-7*||A||F
            if (o2 <= 1e-10f * tot) threshsh = 3.4e38f;   // already converged -> all-inactive
        }
        __syncthreads();
    }
    float thr = threshsh;

    float* cur = Abuf0;
    float* nxt = Abuf1;

    int maxsweep = (t == 0) ? 13 : 5;
    for (int sweep = 0; sweep < maxsweep; sweep++) {
        if (tid == 0) sSweepActive = 0;
        __syncthreads();

        for (int r = 0; r < 63; r++) {
            // phase 1: rotation parameters (warp 0)
            if (tid < 32) {
                int p = (tid == 0) ? 0 : ((tid - 1 + r) % 63) + 1;
                int qpos = 63 - tid;
                int q = ((qpos - 1 + r) % 63) + 1;
                float app = cur[p*LDA + p], aqq = cur[q*LDA + q], apq = cur[p*LDA + q];
                float c = 1.f, s = 0.f;
                bool active = (apq*apq > thr);
                if (active) {
                    float tau = (aqq - app) / (2.f * apq);
                    float tt = 1.f / (fabsf(tau) + sqrtf(fmaf(tau, tau, 1.f)));
                    if (tau < 0.f) tt = -tt;
                    c = rsqrtf(fmaf(tt, tt, 1.f));
                    s = tt * c;
                }
                cs[tid] = c; sn[tid] = s; pA[tid] = p; qA[tid] = q;
                unsigned int m2 = __ballot_sync(0xffffffffu, active);
                if (tid == 0) { sMask = m2; if (m2) sSweepActive = 1; }
            }
            __syncthreads();

            // capture mask in a register between the barriers (race-safe)
            unsigned int m = sMask;
            if (m != 0u) {
                // phase 2a: 2x2 block rotate cur -> nxt (1024 blocks, 2/thread)
                #pragma unroll
                for (int k = 0; k < 2; k++) {
                    int id = tid + k*ETH;
                    int a = id >> 5, bb = id & 31;
                    int pa = pA[a], qa = qA[a];
                    float ca = cs[a], sa = sn[a];
                    int pb = pA[bb], qb = qA[bb];
                    float cb = cs[bb], sb = sn[bb];
                    float t00 = cur[pa*LDA + pb], t01 = cur[pa*LDA + qb];
                    float t10 = cur[qa*LDA + pb], t11 = cur[qa*LDA + qb];
                    float r00 = ca*t00 - sa*t10, r01 = ca*t01 - sa*t11;
                    float r10 = sa*t00 + ca*t10, r11 = sa*t01 + ca*t11;
                    nxt[pa*LDA + pb] = cb*r00 - sb*r01;
                    nxt[pa*LDA + qb] = sb*r00 + cb*r01;
                    nxt[qa*LDA + pb] = cb*r10 - sb*r11;
                    nxt[qa*LDA + qb] = sb*r10 + cb*r11;
                }
                // phase 2b: V <- V*J (in-place safe; 2048 tasks, 4/thread)
                #pragma unroll
                for (int k = 0; k < 4; k++) {
                    int id = tid + k*ETH;
                    int pr = id & 31, i = id >> 5;
                    float s = sn[pr];
                    if (s != 0.f) {
                        float c = cs[pr];
                        int p = pA[pr], q = qA[pr];
                        float v0 = Vv[i*LDA + p], v1 = Vv[i*LDA + q];
                        Vv[i*LDA + p] = c*v0 - s*v1;
                        Vv[i*LDA + q] = s*v0 + c*v1;
                    }
                }
            }
            __syncthreads();
            if (m != 0u) { float* tmp = cur; cur = nxt; nxt = tmp; }  // uniform swap
        }
        // read flag, THEN barrier, THEN break (R10 race fix)
        int sweepDone = (sSweepActive == 0);
        __syncthreads();
        if (sweepDone) break;
    }

    // 4) eigenvalue estimates (diag of cur)
    if (tid < CHA) sdiag[tid] = cur[tid*LDA + tid];
    __syncthreads();

    float* VF;
    if (t > 0) {
        // Vfull = V0 * Vjac  -> into nxt (dead buffer)
        float fac[8];
        #pragma unroll
        for (int j = 0; j < 8; j++) fac[j] = 0.f;
        for (int k = 0; k < CHA; k++) {
            float a = V0v[mi*CHA + k];
            #pragma unroll
            for (int j = 0; j < 8; j++) fac[j] = fmaf(a, Vv[k*LDA + mj+j], fac[j]);
        }
        __syncthreads();
        #pragma unroll
        for (int j = 0; j < 8; j++) nxt[mi*LDA + mj+j] = fac[j];
        __syncthreads();
        VF = nxt;
    } else {
        VF = Vv;
    }

    // 5) store basis + top-3 columns (double-buffered Ur)
    for (int e = tid; e < CHA*CHA; e += ETH)
        g_V[(size_t)b*CHA*CHA + e] = VF[(e>>6)*LDA + (e&63)];

    if (tid == 0) {
        float v0 = -1e30f, v1 = -1e30f, v2 = -1e30f;
        int i0 = 0, i1 = 0, i2 = 0;
        for (int k = 0; k < CHA; k++) {
            float d = sdiag[k];
            if (d > v0)      { v2=v1; i2=i1; v1=v0; i1=i0; v0=d; i0=k; }
            else if (d > v1) { v2=v1; i2=i1; v1=d;  i1=k; }
            else if (d > v2) { v2=d;  i2=k; }
        }
        tidx3[0] = i0; tidx3[1] = i1; tidx3[2] = i2;
    }
    __syncthreads();
    float* urOut = g_Ur[t & 1];
    for (int e = tid; e < CHA*RR; e += ETH) {
        int c = e / RR, rr2 = e % RR;
        urOut[(size_t)b*CHA*RR + e] = VF[c*LDA + tidx3[rr2]];
    }
}

// ---------------- fused: reconstruct L_t, utl_t, losses, L_{t+1} gram ----------------
__global__ __launch_bounds__(NT) void fused_kernel(
    const float* __restrict__ x, const float* __restrict__ W,
    float apPrev, float apCur, int t, int last, float* __restrict__ outUV, int bandOff)
{
    int b = bandOff + blockIdx.y, grp = blockIdx.x, tid = threadIdx.x;
    extern __shared__ float fsm[];
    float (*xs)[NT+2] = (float(*)[NT+2])fsm;                 // x tile, becomes L_{t+1} tile
    float (*ws)[NT+2] = (float(*)[NT+2])(fsm + CHA*(NT+2));  // W tile
    __shared__ float sUrC[CHA*RR], sUrP[CHA*RR];
    __shared__ float sred[8];

    const float* urC = g_Ur[t & 1];
    const float* urP = g_Ur[(t - 1) & 1];
    for (int e = tid; e < CHA*RR; e += NT) {
        sUrC[e] = urC[(size_t)b*CHA*RR + e];
        if (t > 0) sUrP[e] = urP[(size_t)b*CHA*RR + e];
    }
    float rhoP = g_rho0 * apPrev;
    float rhoC = g_rho0 * apCur;
    int ty = tid >> 4, tx = tid & 15;
    ULL acc[8][4];
    #pragma unroll
    for (int i = 0; i < 8; i++)
        #pragma unroll
        for (int j = 0; j < 4; j++) acc[i][j] = 0ULL;
    float lossF = 0.f, lossU = 0.f;
    __syncthreads();

    #pragma unroll 1
    for (int st = 0; st < SUBT; st++) {
        int pix = grp*GROUPN + st*NT + tid;
        size_t base = (size_t)b*CHA*NPIX + pix;
        __syncthreads();
        #pragma unroll 8
        for (int c = 0; c < CHA; c++) {
            size_t idx = base + (size_t)c*NPIX;
            xs[c][tid] = x[idx];
            ws[c][tid] = W[idx];
        }
        float u0 = 0.f, u1 = 0.f, u2 = 0.f;
        if (t == 0) {
            #pragma unroll 8
            for (int c = 0; c < CHA; c++) {
                float v = xs[c][tid];
                u0 = fmaf(sUrC[c*3+0], v, u0);
                u1 = fmaf(sUrC[c*3+1], v, u1);
                u2 = fmaf(sUrC[c*3+2], v, u2);
            }
        } else {
            size_t ub = (size_t)b*RR*NPIX + pix;
            float p0 = g_utl[ub];
            float p1 = g_utl[ub + NPIX];
            float p2 = g_utl[ub + 2*NPIX];
            #pragma unroll 4
            for (int c = 0; c < CHA; c++) {
                float xv = xs[c][tid], wv = ws[c][tid];
                float uvp = fmaf(sUrP[c*3+0], p0, fmaf(sUrP[c*3+1], p1, sUrP[c*3+2]*p2));
                float d = uvp - xv;
                float mu = __fdividef(rhoP, wv + rhoP);
                float lv = fmaf(mu, d, xv);
                u0 = fmaf(sUrC[c*3+0], lv, u0);
                u1 = fmaf(sUrC[c*3+1], lv, u1);
                u2 = fmaf(sUrC[c*3+2], lv, u2);
            }
        }
        lossU += u0*u0 + u1*u1 + u2*u2;

        if (!last) {
            size_t ub = (size_t)b*RR*NPIX + pix;
            g_utl[ub]          = u0;
            g_utl[ub + NPIX]   = u1;
            g_utl[ub + 2*NPIX] = u2;
            #pragma unroll 4
            for (int c = 0; c < CHA; c++) {
                float xv = xs[c][tid], wv = ws[c][tid];
                float uv = fmaf(sUrC[c*3+0], u0, fmaf(sUrC[c*3+1], u1, sUrC[c*3+2]*u2));
                float d = uv - xv;
                lossF = fmaf(wv*d, d, lossF);
                float mu = __fdividef(rhoC, wv + rhoC);
                xs[c][tid] = fmaf(mu, d, xv);
            }
            __syncthreads();
            gram_acc2((const float(*)[NT+2])xs, acc, ty, tx);
        } else {
            #pragma unroll 4
            for (int c = 0; c < CHA; c++) {
                float xv = xs[c][tid], wv = ws[c][tid];
                float uv = fmaf(sUrC[c*3+0], u0, fmaf(sUrC[c*3+1], u1, sUrC[c*3+2]*u2));
                float d = uv - xv;
                lossF = fmaf(wv*d, d, lossF);
                outUV[base + (size_t)c*NPIX] = uv;
            }
        }
    }

    #pragma unroll
    for (int o = 16; o > 0; o >>= 1) {
        lossF += __shfl_xor_sync(0xffffffffu, lossF, o);
        lossU += __shfl_xor_sync(0xffffffffu, lossU, o);
    }
    if ((tid & 31) == 0) { sred[tid>>5] = lossF; sred[4 + (tid>>5)] = lossU; }
    __syncthreads();
    if (tid == 0) {
        float f = sred[0]+sred[1]+sred[2]+sred[3];
        float u = sred[4]+sred[5]+sred[6]+sred[7];
        size_t gi = (size_t)t*BANDS*NGROUPS + (size_t)b*NGROUPS + grp;
        g_lossPart[2*gi]   = f;
        g_lossPart[2*gi+1] = u;
    }

    if (!last)
        gram_store2(g_Gpart + ((size_t)(b*NGROUPS + grp))*CHA*CHA, acc, ty, tx);
}

// ---------------- all per-iteration loss scalars -> d_out tail (after join) ----------------
__global__ void final_loss_kernel(float* __restrict__ out) {
    __shared__ float sf[256], su[256];
    int t = blockIdx.x;
    float f = 0.f, u = 0.f;
    const float* p = g_lossPart + (size_t)t*BANDS*NGROUPS*2;
    for (int i = threadIdx.x; i < BANDS*NGROUPS; i += 256) {
        f += p[2*i];
        u += p[2*i+1];
    }
    sf[threadIdx.x] = f; su[threadIdx.x] = u; __syncthreads();
    for (int o = 128; o > 0; o >>= 1) {
        if (threadIdx.x < o) { sf[threadIdx.x] += sf[threadIdx.x+o]; su[threadIdx.x] += su[threadIdx.x+o]; }
        __syncthreads();
    }
    if (threadIdx.x == 0) {
        float inv = 1.f / (float)TOTELEM;
        out[TOTELEM + t]        = sf[0] * inv;   // loss_F
        out[TOTELEM + NITE + t] = su[0] * inv;   // loss
    }
}

// ---------------- launch: 4 band-chunks on 4 streams, fork/join via events ----------------
extern "C" void kernel_launch(void* const* d_in, const int* in_sizes, int n_in,
                              void* d_out, int out_size) {
    (void)in_sizes; (void)n_in; (void)out_size;
    const float* x = (const float*)d_in[0];
    const float* W = (const float*)d_in[1];
    float* out = (float*)d_out;

    const int ESMEM = (3*CHA*LDA + CHA*CHA) * (int)sizeof(float);      // 66304 B
    const int FSMEM = 2*CHA*(NT+2) * (int)sizeof(float);               // 66560 B

    static cudaStream_t side[NCHUNK-1];
    static cudaEvent_t  evFork, evJoin[NCHUNK-1];
    static int init_done = 0;
    if (!init_done) {
        cudaFuncSetAttribute(eig_kernel,   cudaFuncAttributeMaxDynamicSharedMemorySize, ESMEM);
        cudaFuncSetAttribute(fused_kernel, cudaFuncAttributeMaxDynamicSharedMemorySize, FSMEM);
        for (int i = 0; i < NCHUNK-1; i++)
            cudaStreamCreateWithFlags(&side[i], cudaStreamNonBlocking);
        cudaEventCreateWithFlags(&evFork, cudaEventDisableTiming);
        for (int i = 0; i < NCHUNK-1; i++)
            cudaEventCreateWithFlags(&evJoin[i], cudaEventDisableTiming);
        init_done = 1;
    }

    // prologue on the main (capture) stream
    wsum_part_kernel<<<1024, 256>>>(W);
    wsum_final_kernel<<<1, 256>>>();

    // fork
    cudaEventRecord(evFork, 0);
    for (int i = 0; i < NCHUNK-1; i++)
        cudaStreamWaitEvent(side[i], evFork, 0);

    // independent per-chunk chains
    for (int ck = 0; ck < NCHUNK; ck++) {
        cudaStream_t st = (ck == 0) ? (cudaStream_t)0 : side[ck-1];
        int off = ck * BPC;
        dim3 gGram(NGROUPS, BPC);
        syrk0_kernel<<<gGram, NT, 0, st>>>(x, off);
        float ap = 1.0f, apPrev = 1.0f;
        for (int t = 0; t < NITE; t++) {
            eig_kernel<<<BPC, ETH, ESMEM, st>>>(t, off);
            fused_kernel<<<gGram, NT, FSMEM, st>>>(x, W, apPrev, ap, t,
                                                   (t == NITE-1) ? 1 : 0, out, off);
            apPrev = ap;
            ap *= 1.05f;   // matches reference's fp32 rho *= 1.05 recurrence
        }
    }

    // join
    for (int i = 0; i < NCHUNK-1; i++) {
        cudaEventRecord(evJoin[i], side[i]);
        cudaStreamWaitEvent((cudaStream_t)0, evJoin[i], 0);
    }

    // all 40 loss scalars in one launch
    final_loss_kernel<<<NITE, 256>>>(out);
}

// round 16
// speedup vs baseline: 1.3557x; 1.2532x over previous
#include <cuda_runtime.h>

// ---------------- problem constants ----------------
#define BANDS 64
#define CHA   64
#define NPIX  16384
#define RR    3
#define NITE  20
#define NT    128                 // pixel sub-tile width (threads per block)
#define SUBT  4                   // sub-tiles per block
#define GROUPN (NT*SUBT)          // 512 pixels per block
#define NGROUPS (NPIX/GROUPN)     // 32 groups per band
#define NCHUNK 4                  // band chunks / streams (3 side streams pass the mem checkpoint)
#define BPC   (BANDS/NCHUNK)      // 16 bands per chunk
#define TOTELEM ((size_t)BANDS*CHA*NPIX)  // 67,108,864
#define LDA   (CHA+1)             // 65: smem row stride for eig matrices
typedef unsigned long long ULL;

// ---------------- device scratch (no allocs allowed) ----------------
__device__ float g_utl[BANDS*RR*NPIX];             // 12.6 MB
__device__ float g_Gpart[BANDS*NGROUPS*CHA*CHA];   // 33.5 MB
__device__ float g_V[BANDS*CHA*CHA];               // 1 MB   (warm-start eigenbasis)
__device__ float g_Ur[2][BANDS*CHA*RR];            // double-buffered top-3 basis
__device__ float g_lossPart[NITE*BANDS*NGROUPS*2]; // per-iteration loss partials
__device__ float g_wpart[1024];
__device__ float g_rho0;

// ---------------- packed f32x2 helpers (SASS FFMA2; PTX-only pattern) ----------------
__device__ __forceinline__ void ffma2(ULL& acc, ULL a, ULL b) {
    asm("fma.rn.f32x2 %0, %1, %2, %0;" : "+l"(acc) : "l"(a), "l"(b));
}
__device__ __forceinline__ void unpack2(ULL v, float& lo, float& hi) {
    unsigned int a, b;
    asm("mov.b64 {%0, %1}, %2;" : "=r"(a), "=r"(b) : "l"(v));
    lo = __uint_as_float(a); hi = __uint_as_float(b);
}

// ---------------- mean(W) reduction ----------------
__global__ void wsum_part_kernel(const float* __restrict__ W) {
    __shared__ float sred[256];
    float s = 0.f;
    size_t stride = (size_t)gridDim.x * blockDim.x;
    for (size_t i = (size_t)blockIdx.x*blockDim.x + threadIdx.x; i < TOTELEM; i += stride)
        s += W[i];
    sred[threadIdx.x] = s; __syncthreads();
    for (int o = 128; o > 0; o >>= 1) {
        if (threadIdx.x < o) sred[threadIdx.x] += sred[threadIdx.x+o];
        __syncthreads();
    }
    if (threadIdx.x == 0) g_wpart[blockIdx.x] = sred[0];
}

__global__ void wsum_final_kernel() {
    __shared__ float sred[256];
    float s = 0.f;
    for (int i = threadIdx.x; i < 1024; i += 256) s += g_wpart[i];
    sred[threadIdx.x] = s; __syncthreads();
    for (int o = 128; o > 0; o >>= 1) {
        if (threadIdx.x < o) sred[threadIdx.x] += sred[threadIdx.x+o];
        __syncthreads();
    }
    if (threadIdx.x == 0) g_rho0 = 0.5f * sred[0] / (float)TOTELEM;
}

// ---------------- gram accumulate, paired-n FFMA2, conflict-free ----------------
__device__ __forceinline__ void gram_acc2(const float (*sL)[NT+2], ULL acc[8][4], int ty, int tx) {
    #pragma unroll 2
    for (int n = 0; n < NT; n += 2) {
        ULL a2[8], b2[4];
        #pragma unroll
        for (int i = 0; i < 8; i++) a2[i] = *(const ULL*)&sL[ty + 8*i][n];
        #pragma unroll
        for (int j = 0; j < 4; j++) b2[j] = *(const ULL*)&sL[tx + 16*j][n];
        #pragma unroll
        for (int i = 0; i < 8; i++)
            #pragma unroll
            for (int j = 0; j < 4; j++)
                ffma2(acc[i][j], a2[i], b2[j]);
    }
}

__device__ __forceinline__ void gram_store2(float* out, ULL acc[8][4], int ty, int tx) {
    #pragma unroll
    for (int i = 0; i < 8; i++)
        #pragma unroll
        for (int j = 0; j < 4; j++) {
            float lo, hi; unpack2(acc[i][j], lo, hi);
            out[(ty + 8*i)*CHA + tx + 16*j] = lo + hi;
        }
}

// ---------------- G0 = x x^T (partials) ----------------
__global__ __launch_bounds__(NT) void syrk0_kernel(const float* __restrict__ src, int bandOff) {
    int b = bandOff + blockIdx.y, grp = blockIdx.x, tid = threadIdx.x;
    __shared__ float sL[CHA][NT+2];
    int ty = tid >> 4, tx = tid & 15;
    ULL acc[8][4];
    #pragma unroll
    for (int i = 0; i < 8; i++)
        #pragma unroll
        for (int j = 0; j < 4; j++) acc[i][j] = 0ULL;

    size_t base = (size_t)b*CHA*NPIX + (size_t)grp*GROUPN;
    for (int st = 0; st < SUBT; st++) {
        __syncthreads();
        #pragma unroll 4
        for (int c = 0; c < CHA; c++)
            sL[c][tid] = src[base + (size_t)c*NPIX + st*NT + tid];
        __syncthreads();
        gram_acc2(sL, acc, ty, tx);
    }
    gram_store2(g_Gpart + ((size_t)(b*NGROUPS + grp))*CHA*CHA, acc, ty, tx);
}

// ---------------- warm-started Jacobi, fused 2x2-block rounds (2 barriers/round) ----------------
#define ETH 512
__global__ __launch_bounds__(ETH) void eig_kernel(int t, int bandOff) {
    int b = bandOff + blockIdx.x, tid = threadIdx.x;
    extern __shared__ float esm[];
    float* Abuf0 = esm;                       // 64x65
    float* Abuf1 = esm + CHA*LDA;             // 64x65
    float* Vv    = esm + 2*CHA*LDA;           // 64x65
    float* V0v   = esm + 3*CHA*LDA;           // 64x64
    __shared__ float cs[32], sn[32];
    __shared__ int   pA[32], qA[32];
    __shared__ float red1[ETH/32], red2[ETH/32];
    __shared__ float threshsh;
    __shared__ unsigned int sMask;
    __shared__ int   sSweepActive;
    __shared__ float sdiag[CHA];
    __shared__ int   tidx3[3];

    // 1) reduce gram partials for this band into Abuf0
    const float* P = g_Gpart + (size_t)b*NGROUPS*CHA*CHA;
    for (int e = tid; e < CHA*CHA; e += ETH) {
        float s = 0.f;
        #pragma unroll
        for (int g2 = 0; g2 < NGROUPS; g2++) s += P[(size_t)g2*CHA*CHA + e];
        Abuf0[(e>>6)*LDA + (e&63)] = s;
        if (t > 0) V0v[e] = g_V[(size_t)b*CHA*CHA + e];
    }
    __syncthreads();

    int mi = tid >> 3;          // 0..63
    int mj = (tid & 7) * 8;     // 0,8,..,56

    // 2) warm start: A <- V0^T A V0  (temp = Abuf1)
    if (t > 0) {
        float tac[8];
        #pragma unroll
        for (int j = 0; j < 8; j++) tac[j] = 0.f;
        for (int k = 0; k < CHA; k++) {
            float a = Abuf0[mi*LDA + k];
            #pragma unroll
            for (int j = 0; j < 8; j++) tac[j] = fmaf(a, V0v[k*CHA + mj+j], tac[j]);
        }
        #pragma unroll
        for (int j = 0; j < 8; j++) Abuf1[mi*LDA + mj+j] = tac[j];   // T = A*V0
        __syncthreads();
        float tac2[8];
        #pragma unroll
        for (int j = 0; j < 8; j++) tac2[j] = 0.f;
        for (int k = 0; k < CHA; k++) {
            float a = V0v[k*CHA + mi];
            #pragma unroll
            for (int j = 0; j < 8; j++) tac2[j] = fmaf(a, Abuf1[k*LDA + mj+j], tac2[j]);
        }
        __syncthreads();
        #pragma unroll
        for (int j = 0; j < 8; j++) Abuf0[mi*LDA + mj+j] = tac2[j];  // A <- V0^T T
        __syncthreads();
    }

    // 3) V <- I ; one-time norms + threshold (||A||F invariant under rotations)
    {
        float off = 0.f, dg = 0.f;
        for (int e = tid; e < CHA*CHA; e += ETH) {
            int i = e >> 6, j = e & 63;
            Vv[i*LDA + j] = (i == j) ? 1.f : 0.f;
            float v = Abuf0[i*LDA + j];
            if (i == j) dg += v*v; else off += v*v;
        }
        #pragma unroll
        for (int o = 16; o > 0; o >>= 1) {
            off += __shfl_xor_sync(0xffffffffu, off, o);
            dg  += __shfl_xor_sync(0xffffffffu, dg, o);
        }
        if ((tid & 31) == 0) { red1[tid>>5] = off; red2[tid>>5] = dg; }
        __syncthreads();
        if (tid == 0) {
            float o2 = 0.f, d2 = 0.f;
            for (int i2 = 0; i2 < ETH/32; i2++) { o2 += red1[i2]; d2 += red2[i2]; }
            float tot = o2 + d2;
            threshsh = 6e-13f * tot;      // apq <= ~7.7e-7*||A||F (12x looser; measured +0.5e-4 per 10x)
            if (o2 <= 1.3e-9f * tot) threshsh = 3.4e38f;  // <= post-sweep residual -> all-inactive exit
        }
        __syncthreads();
    }
    float thr = threshsh;

    float* cur = Abuf0;
    float* nxt = Abuf1;

    int maxsweep = (t == 0) ? 13 : 5;
    for (int sweep = 0; sweep < maxsweep; sweep++) {
        if (tid == 0) sSweepActive = 0;
        __syncthreads();

        for (int r = 0; r < 63; r++) {
            // phase 1: rotation parameters (warp 0)
            if (tid < 32) {
                int p = (tid == 0) ? 0 : ((tid - 1 + r) % 63) + 1;
                int qpos = 63 - tid;
                int q = ((qpos - 1 + r) % 63) + 1;
                float app = cur[p*LDA + p], aqq = cur[q*LDA + q], apq = cur[p*LDA + q];
                float c = 1.f, s = 0.f;
                bool active = (apq*apq > thr);
                if (active) {
                    float tau = (aqq - app) / (2.f * apq);
                    float tt = 1.f / (fabsf(tau) + sqrtf(fmaf(tau, tau, 1.f)));
                    if (tau < 0.f) tt = -tt;
                    c = rsqrtf(fmaf(tt, tt, 1.f));
                    s = tt * c;
                }
                cs[tid] = c; sn[tid] = s; pA[tid] = p; qA[tid] = q;
                unsigned int m2 = __ballot_sync(0xffffffffu, active);
                if (tid == 0) { sMask = m2; if (m2) sSweepActive = 1; }
            }
            __syncthreads();

            // capture mask in a register between the barriers (race-safe)
            unsigned int m = sMask;
            if (m != 0u) {
                // phase 2a: 2x2 block rotate cur -> nxt (1024 blocks, 2/thread)
                #pragma unroll
                for (int k = 0; k < 2; k++) {
                    int id = tid + k*ETH;
                    int a = id >> 5, bb = id & 31;
                    int pa = pA[a], qa = qA[a];
                    float ca = cs[a], sa = sn[a];
                    int pb = pA[bb], qb = qA[bb];
                    float cb = cs[bb], sb = sn[bb];
                    float t00 = cur[pa*LDA + pb], t01 = cur[pa*LDA + qb];
                    float t10 = cur[qa*LDA + pb], t11 = cur[qa*LDA + qb];
                    float r00 = ca*t00 - sa*t10, r01 = ca*t01 - sa*t11;
                    float r10 = sa*t00 + ca*t10, r11 = sa*t01 + ca*t11;
                    nxt[pa*LDA + pb] = cb*r00 - sb*r01;
                    nxt[pa*LDA + qb] = sb*r00 + cb*r01;
                    nxt[qa*LDA + pb] = cb*r10 - sb*r11;
                    nxt[qa*LDA + qb] = sb*r10 + cb*r11;
                }
                // phase 2b: V <- V*J (in-place safe; 2048 tasks, 4/thread)
                #pragma unroll
                for (int k = 0; k < 4; k++) {
                    int id = tid + k*ETH;
                    int pr = id & 31, i = id >> 5;
                    float s = sn[pr];
                    if (s != 0.f) {
                        float c = cs[pr];
                        int p = pA[pr], q = qA[pr];
                        float v0 = Vv[i*LDA + p], v1 = Vv[i*LDA + q];
                        Vv[i*LDA + p] = c*v0 - s*v1;
                        Vv[i*LDA + q] = s*v0 + c*v1;
                    }
                }
            }
            __syncthreads();
            if (m != 0u) { float* tmp = cur; cur = nxt; nxt = tmp; }  // uniform swap
        }
        // read flag, THEN barrier, THEN break (R10 race fix)
        int sweepDone = (sSweepActive == 0);
        __syncthreads();
        if (sweepDone) break;
    }

    // 4) eigenvalue estimates (diag of cur)
    if (tid < CHA) sdiag[tid] = cur[tid*LDA + tid];
    __syncthreads();

    float* VF;
    if (t > 0) {
        // Vfull = V0 * Vjac  -> into nxt (dead buffer)
        float fac[8];
        #pragma unroll
        for (int j = 0; j < 8; j++) fac[j] = 0.f;
        for (int k = 0; k < CHA; k++) {
            float a = V0v[mi*CHA + k];
            #pragma unroll
            for (int j = 0; j < 8; j++) fac[j] = fmaf(a, Vv[k*LDA + mj+j], fac[j]);
        }
        __syncthreads();
        #pragma unroll
        for (int j = 0; j < 8; j++) nxt[mi*LDA + mj+j] = fac[j];
        __syncthreads();
        VF = nxt;
    } else {
        VF = Vv;
    }

    // 5) store basis + top-3 columns (double-buffered Ur)
    for (int e = tid; e < CHA*CHA; e += ETH)
        g_V[(size_t)b*CHA*CHA + e] = VF[(e>>6)*LDA + (e&63)];

    if (tid == 0) {
        float v0 = -1e30f, v1 = -1e30f, v2 = -1e30f;
        int i0 = 0, i1 = 0, i2 = 0;
        for (int k = 0; k < CHA; k++) {
            float d = sdiag[k];
            if (d > v0)      { v2=v1; i2=i1; v1=v0; i1=i0; v0=d; i0=k; }
            else if (d > v1) { v2=v1; i2=i1; v1=d;  i1=k; }
            else if (d > v2) { v2=d;  i2=k; }
        }
        tidx3[0] = i0; tidx3[1] = i1; tidx3[2] = i2;
    }
    __syncthreads();
    float* urOut = g_Ur[t & 1];
    for (int e = tid; e < CHA*RR; e += ETH) {
        int c = e / RR, rr2 = e % RR;
        urOut[(size_t)b*CHA*RR + e] = VF[c*LDA + tidx3[rr2]];
    }
}

// ---------------- fused: reconstruct L_t, utl_t, losses, L_{t+1} gram ----------------
__global__ __launch_bounds__(NT) void fused_kernel(
    const float* __restrict__ x, const float* __restrict__ W,
    float apPrev, float apCur, int t, int last, float* __restrict__ outUV, int bandOff)
{
    int b = bandOff + blockIdx.y, grp = blockIdx.x, tid = threadIdx.x;
    extern __shared__ float fsm[];
    float (*xs)[NT+2] = (float(*)[NT+2])fsm;                 // x tile, becomes L_{t+1} tile
    float (*ws)[NT+2] = (float(*)[NT+2])(fsm + CHA*(NT+2));  // W tile
    __shared__ float sUrC[CHA*RR], sUrP[CHA*RR];
    __shared__ float sred[8];

    const float* urC = g_Ur[t & 1];
    const float* urP = g_Ur[(t - 1) & 1];
    for (int e = tid; e < CHA*RR; e += NT) {
        sUrC[e] = urC[(size_t)b*CHA*RR + e];
        if (t > 0) sUrP[e] = urP[(size_t)b*CHA*RR + e];
    }
    float rhoP = g_rho0 * apPrev;
    float rhoC = g_rho0 * apCur;
    int ty = tid >> 4, tx = tid & 15;
    ULL acc[8][4];
    #pragma unroll
    for (int i = 0; i < 8; i++)
        #pragma unroll
        for (int j = 0; j < 4; j++) acc[i][j] = 0ULL;
    float lossF = 0.f, lossU = 0.f;
    __syncthreads();

    #pragma unroll 1
    for (int st = 0; st < SUBT; st++) {
        int pix = grp*GROUPN + st*NT + tid;
        size_t base = (size_t)b*CHA*NPIX + pix;
        __syncthreads();
        #pragma unroll 8
        for (int c = 0; c < CHA; c++) {
            size_t idx = base + (size_t)c*NPIX;
            xs[c][tid] = x[idx];
            ws[c][tid] = W[idx];
        }
        float u0 = 0.f, u1 = 0.f, u2 = 0.f;
        if (t == 0) {
            #pragma unroll 8
            for (int c = 0; c < CHA; c++) {
                float v = xs[c][tid];
                u0 = fmaf(sUrC[c*3+0], v, u0);
                u1 = fmaf(sUrC[c*3+1], v, u1);
                u2 = fmaf(sUrC[c*3+2], v, u2);
            }
        } else {
            size_t ub = (size_t)b*RR*NPIX + pix;
            float p0 = g_utl[ub];
            float p1 = g_utl[ub + NPIX];
            float p2 = g_utl[ub + 2*NPIX];
            #pragma unroll 4
            for (int c = 0; c < CHA; c++) {
                float xv = xs[c][tid], wv = ws[c][tid];
                float uvp = fmaf(sUrP[c*3+0], p0, fmaf(sUrP[c*3+1], p1, sUrP[c*3+2]*p2));
                float d = uvp - xv;
                float mu = __fdividef(rhoP, wv + rhoP);
                float lv = fmaf(mu, d, xv);
                u0 = fmaf(sUrC[c*3+0], lv, u0);
                u1 = fmaf(sUrC[c*3+1], lv, u1);
                u2 = fmaf(sUrC[c*3+2], lv, u2);
            }
        }
        lossU += u0*u0 + u1*u1 + u2*u2;

        if (!last) {
            size_t ub = (size_t)b*RR*NPIX + pix;
            g_utl[ub]          = u0;
            g_utl[ub + NPIX]   = u1;
            g_utl[ub + 2*NPIX] = u2;
            #pragma unroll 4
            for (int c = 0; c < CHA; c++) {
                float xv = xs[c][tid], wv = ws[c][tid];
                float uv = fmaf(sUrC[c*3+0], u0, fmaf(sUrC[c*3+1], u1, sUrC[c*3+2]*u2));
                float d = uv - xv;
                lossF = fmaf(wv*d, d, lossF);
                float mu = __fdividef(rhoC, wv + rhoC);
                xs[c][tid] = fmaf(mu, d, xv);
            }
            __syncthreads();
            gram_acc2((const float(*)[NT+2])xs, acc, ty, tx);
        } else {
            #pragma unroll 4
            for (int c = 0; c < CHA; c++) {
                float xv = xs[c][tid], wv = ws[c][tid];
                float uv = fmaf(sUrC[c*3+0], u0, fmaf(sUrC[c*3+1], u1, sUrC[c*3+2]*u2));
                float d = uv - xv;
                lossF = fmaf(wv*d, d, lossF);
                outUV[base + (size_t)c*NPIX] = uv;
            }
        }
    }

    #pragma unroll
    for (int o = 16; o > 0; o >>= 1) {
        lossF += __shfl_xor_sync(0xffffffffu, lossF, o);
        lossU += __shfl_xor_sync(0xffffffffu, lossU, o);
    }
    if ((tid & 31) == 0) { sred[tid>>5] = lossF; sred[4 + (tid>>5)] = lossU; }
    __syncthreads();
    if (tid == 0) {
        float f = sred[0]+sred[1]+sred[2]+sred[3];
        float u = sred[4]+sred[5]+sred[6]+sred[7];
        size_t gi = (size_t)t*BANDS*NGROUPS + (size_t)b*NGROUPS + grp;
        g_lossPart[2*gi]   = f;
        g_lossPart[2*gi+1] = u;
    }

    if (!last)
        gram_store2(g_Gpart + ((size_t)(b*NGROUPS + grp))*CHA*CHA, acc, ty, tx);
}

// ---------------- all per-iteration loss scalars -> d_out tail (after join) ----------------
__global__ void final_loss_kernel(float* __restrict__ out) {
    __shared__ float sf[256], su[256];
    int t = blockIdx.x;
    float f = 0.f, u = 0.f;
    const float* p = g_lossPart + (size_t)t*BANDS*NGROUPS*2;
    for (int i = threadIdx.x; i < BANDS*NGROUPS; i += 256) {
        f += p[2*i];
        u += p[2*i+1];
    }
    sf[threadIdx.x] = f; su[threadIdx.x] = u; __syncthreads();
    for (int o = 128; o > 0; o >>= 1) {
        if (threadIdx.x < o) { sf[threadIdx.x] += sf[threadIdx.x+o]; su[threadIdx.x] += su[threadIdx.x+o]; }
        __syncthreads();
    }
    if (threadIdx.x == 0) {
        float inv = 1.f / (float)TOTELEM;
        out[TOTELEM + t]        = sf[0] * inv;   // loss_F
        out[TOTELEM + NITE + t] = su[0] * inv;   // loss
    }
}

// ---------------- launch: 4 staggered band-chunks on 4 streams ----------------
extern "C" void kernel_launch(void* const* d_in, const int* in_sizes, int n_in,
                              void* d_out, int out_size) {
    (void)in_sizes; (void)n_in; (void)out_size;
    const float* x = (const float*)d_in[0];
    const float* W = (const float*)d_in[1];
    float* out = (float*)d_out;

    const int ESMEM = (3*CHA*LDA + CHA*CHA) * (int)sizeof(float);      // 66304 B
    const int FSMEM = 2*CHA*(NT+2) * (int)sizeof(float);               // 66560 B

    static cudaStream_t side[NCHUNK-1];
    static cudaEvent_t  evFork, evJoin[NCHUNK-1], evSkew[NCHUNK-1];
    static int init_done = 0;
    if (!init_done) {
        cudaFuncSetAttribute(eig_kernel,   cudaFuncAttributeMaxDynamicSharedMemorySize, ESMEM);
        cudaFuncSetAttribute(fused_kernel, cudaFuncAttributeMaxDynamicSharedMemorySize, FSMEM);
        for (int i = 0; i < NCHUNK-1; i++)
            cudaStreamCreateWithFlags(&side[i], cudaStreamNonBlocking);
        cudaEventCreateWithFlags(&evFork, cudaEventDisableTiming);
        for (int i = 0; i < NCHUNK-1; i++) {
            cudaEventCreateWithFlags(&evJoin[i], cudaEventDisableTiming);
            cudaEventCreateWithFlags(&evSkew[i], cudaEventDisableTiming);
        }
        init_done = 1;
    }

    // prologue on the main (capture) stream
    wsum_part_kernel<<<1024, 256>>>(W);
    wsum_final_kernel<<<1, 256>>>();

    // fork
    cudaEventRecord(evFork, 0);
    for (int i = 0; i < NCHUNK-1; i++)
        cudaStreamWaitEvent(side[i], evFork, 0);

    // independent per-chunk chains, staggered by ~one syrk0 each to break lockstep
    for (int ck = 0; ck < NCHUNK; ck++) {
        cudaStream_t st = (ck == 0) ? (cudaStream_t)0 : side[ck-1];
        int off = ck * BPC;
        dim3 gGram(NGROUPS, BPC);
        if (ck > 0) cudaStreamWaitEvent(st, evSkew[ck-1], 0);   // skew: wait prev chunk's syrk0
        syrk0_kernel<<<gGram, NT, 0, st>>>(x, off);
        if (ck < NCHUNK-1) cudaEventRecord(evSkew[ck], st);
        float ap = 1.0f, apPrev = 1.0f;
        for (int t = 0; t < NITE; t++) {
            eig_kernel<<<BPC, ETH, ESMEM, st>>>(t, off);
            fused_kernel<<<gGram, NT, FSMEM, st>>>(x, W, apPrev, ap, t,
                                                   (t == NITE-1) ? 1 : 0, out, off);
            apPrev = ap;
            ap *= 1.05f;   // matches reference's fp32 rho *= 1.05 recurrence
        }
    }

    // join
    for (int i = 0; i < NCHUNK-1; i++) {
        cudaEventRecord(evJoin[i], side[i]);
        cudaStreamWaitEvent((cudaStream_t)0, evJoin[i], 0);
    }

    // all 40 loss scalars in one launch
    final_loss_kernel<<<NITE, 256>>>(out);
}